// round 11
// baseline (speedup 1.0000x reference)
#include <cuda_runtime.h>
#include <math.h>

#define NN 500000
#define NE 8000000

// Scratch (device globals — zero-initialized at load; g_deg is re-zeroed by
// k_prep after each use, so every kernel_launch call sees deg==0 on entry).
__device__ float g_deg[NN];
__device__ float g_dinv[NN];
__device__ float g_p[NN];            // x*dinv
__device__ float g_a1[NN];           // layer-1 accumulator, seeded with p (self-loop)
__device__ float2 g_q[NN];           // z*dinv per node (2 floats)
__device__ float2 g_a2[NN];          // layer-2 accumulator, seeded with q (self-loop)

// ---------------- count in-degree over dst (4 edges/thread) ----------------
__global__ void __launch_bounds__(128) k_count(const int* __restrict__ dst, int ne) {
    int i = blockIdx.x * blockDim.x + threadIdx.x;
    int e = i * 4;
    if (e + 4 <= ne) {
        int4 d = *reinterpret_cast<const int4*>(dst + e);
        atomicAdd(&g_deg[d.x], 1.0f);
        atomicAdd(&g_deg[d.y], 1.0f);
        atomicAdd(&g_deg[d.z], 1.0f);
        atomicAdd(&g_deg[d.w], 1.0f);
    } else {
        for (; e < ne; e++) atomicAdd(&g_deg[dst[e]], 1.0f);
    }
}

// -- dinv = rsqrt(deg+1); p = x*dinv; a1 = p (self-loop); deg re-zeroed; 4/thread --
__global__ void __launch_bounds__(256) k_prep(const float* __restrict__ x, int n) {
    int i = blockIdx.x * blockDim.x + threadIdx.x;
    int j = i * 4;
    if (j + 4 <= n) {
        // independent: input x (not written by k_count)
        float4 xv = *reinterpret_cast<const float4*>(x + j);
        cudaGridDependencySynchronize();   // wait for k_count's deg writes
        float4 dg = *reinterpret_cast<const float4*>(g_deg + j);
        float4 dv;
        dv.x = rsqrtf(dg.x + 1.0f);
        dv.y = rsqrtf(dg.y + 1.0f);
        dv.z = rsqrtf(dg.z + 1.0f);
        dv.w = rsqrtf(dg.w + 1.0f);
        *reinterpret_cast<float4*>(g_dinv + j) = dv;
        float4 pv = make_float4(xv.x * dv.x, xv.y * dv.y, xv.z * dv.z, xv.w * dv.w);
        *reinterpret_cast<float4*>(g_p + j) = pv;
        *reinterpret_cast<float4*>(g_a1 + j) = pv;   // self-loop contribution
        *reinterpret_cast<float4*>(g_deg + j) = make_float4(0.f, 0.f, 0.f, 0.f);
    } else if (j < n) {
        cudaGridDependencySynchronize();
        for (; j < n; j++) {
            float dv = rsqrtf(g_deg[j] + 1.0f);
            g_dinv[j] = dv;
            float pv = x[j] * dv;
            g_p[j] = pv;
            g_a1[j] = pv;
            g_deg[j] = 0.0f;
        }
    } else {
        cudaGridDependencySynchronize();
    }
}

// ---------------- layer-1 scalar scatter: a1[dst] += p[src] (4 edges/thread) --
__global__ void __launch_bounds__(128) k_scatter1(const int* __restrict__ src,
                                                  const int* __restrict__ dst, int ne) {
    int i = blockIdx.x * blockDim.x + threadIdx.x;
    int e = i * 4;
    if (e + 4 <= ne) {
        // independent: edge indices (input buffer, untouched by k_prep)
        int4 s = *reinterpret_cast<const int4*>(src + e);
        int4 d = *reinterpret_cast<const int4*>(dst + e);
        cudaGridDependencySynchronize();   // wait for k_prep's p/a1 writes
        float p0 = __ldcg(&g_p[s.x]);
        float p1 = __ldcg(&g_p[s.y]);
        float p2 = __ldcg(&g_p[s.z]);
        float p3 = __ldcg(&g_p[s.w]);
        atomicAdd(&g_a1[d.x], p0);
        atomicAdd(&g_a1[d.y], p1);
        atomicAdd(&g_a1[d.z], p2);
        atomicAdd(&g_a1[d.w], p3);
    } else {
        cudaGridDependencySynchronize();
        for (; e < ne; e++) atomicAdd(&g_a1[dst[e]], __ldcg(&g_p[src[e]]));
    }
}

// ---- per-node MLP (2 nodes/thread): q = dinv*(relu(dinv*a1*W1+b1)@W2); a2 = q ----
__global__ void __launch_bounds__(256) k_node(const float* __restrict__ W1,
                                              const float* __restrict__ b1,
                                              const float* __restrict__ W2, int n) {
    __shared__ float sW1[16], sb1[16], sW2[32];
    int t = threadIdx.x;
    if (t < 16) { sW1[t] = W1[t]; sb1[t] = b1[t]; }
    if (t < 32) { sW2[t] = W2[t]; }
    __syncthreads();
    cudaGridDependencySynchronize();       // wait for k_scatter1's a1 REDs
    int i = blockIdx.x * blockDim.x + t;
    int j = i * 2;
    if (j + 2 <= n) {
        float2 dv = *reinterpret_cast<const float2*>(g_dinv + j);
        float2 a1 = *reinterpret_cast<const float2*>(g_a1 + j);
        float s1a = dv.x * a1.x;
        float s1b = dv.y * a1.y;
        float z0a = 0.0f, z1a = 0.0f, z0b = 0.0f, z1b = 0.0f;
        #pragma unroll
        for (int k = 0; k < 16; k++) {
            float w1 = sW1[k], bb = sb1[k];
            float w20 = sW2[2 * k + 0], w21 = sW2[2 * k + 1];
            float ha = fmaxf(fmaf(s1a, w1, bb), 0.0f);
            float hb = fmaxf(fmaf(s1b, w1, bb), 0.0f);
            z0a = fmaf(ha, w20, z0a);
            z1a = fmaf(ha, w21, z1a);
            z0b = fmaf(hb, w20, z0b);
            z1b = fmaf(hb, w21, z1b);
        }
        float4 qq = make_float4(z0a * dv.x, z1a * dv.x, z0b * dv.y, z1b * dv.y);
        *reinterpret_cast<float4*>(reinterpret_cast<float*>(g_q) + 2 * j) = qq;
        *reinterpret_cast<float4*>(reinterpret_cast<float*>(g_a2) + 2 * j) = qq; // self-loop
    } else if (j < n) {
        float dv = g_dinv[j];
        float s1 = dv * g_a1[j];
        float z0 = 0.0f, z1 = 0.0f;
        #pragma unroll
        for (int k = 0; k < 16; k++) {
            float h = fmaxf(fmaf(s1, sW1[k], sb1[k]), 0.0f);
            z0 = fmaf(h, sW2[2 * k + 0], z0);
            z1 = fmaf(h, sW2[2 * k + 1], z1);
        }
        float2 qq = make_float2(z0 * dv, z1 * dv);
        g_q[j] = qq;
        g_a2[j] = qq;
    }
}

// ---------------- layer-2 vector scatter: a2[dst] += q[src] (float2 RED) ----
__global__ void __launch_bounds__(128) k_scatter2(const int* __restrict__ src,
                                                  const int* __restrict__ dst, int ne) {
    int i = blockIdx.x * blockDim.x + threadIdx.x;
    int e = i * 4;
    if (e + 4 <= ne) {
        int4 s = *reinterpret_cast<const int4*>(src + e);
        int4 d = *reinterpret_cast<const int4*>(dst + e);
        cudaGridDependencySynchronize();   // wait for k_node's q/a2 writes
        float2 q0 = __ldcg(&g_q[s.x]);
        float2 q1 = __ldcg(&g_q[s.y]);
        float2 q2 = __ldcg(&g_q[s.z]);
        float2 q3 = __ldcg(&g_q[s.w]);
        atomicAdd(&g_a2[d.x], q0);
        atomicAdd(&g_a2[d.y], q1);
        atomicAdd(&g_a2[d.z], q2);
        atomicAdd(&g_a2[d.w], q3);
    } else {
        cudaGridDependencySynchronize();
        for (; e < ne; e++) {
            atomicAdd(&g_a2[dst[e]], __ldcg(&g_q[src[e]]));
        }
    }
}

// ---------- finalize: out = log_softmax(dinv*a2 + b2), 2 nodes/thread ----------
__global__ void __launch_bounds__(256) k_final(const float* __restrict__ b2,
                                               float* __restrict__ out, int n) {
    int i = blockIdx.x * blockDim.x + threadIdx.x;
    int j = i * 2;
    float bb0 = __ldg(&b2[0]), bb1 = __ldg(&b2[1]);
    cudaGridDependencySynchronize();       // wait for k_scatter2's a2 REDs
    if (j + 2 <= n) {
        float2 dv2 = *reinterpret_cast<const float2*>(g_dinv + j);
        float4 a = *reinterpret_cast<const float4*>(reinterpret_cast<const float*>(g_a2) + 2 * j);
        float v0 = fmaf(dv2.x, a.x, bb0);
        float v1 = fmaf(dv2.x, a.y, bb1);
        float m0 = fmaxf(v0, v1);
        float l0 = m0 + __logf(__expf(v0 - m0) + __expf(v1 - m0));
        float v2 = fmaf(dv2.y, a.z, bb0);
        float v3 = fmaf(dv2.y, a.w, bb1);
        float m1 = fmaxf(v2, v3);
        float l1 = m1 + __logf(__expf(v2 - m1) + __expf(v3 - m1));
        *reinterpret_cast<float4*>(out + 2 * j) =
            make_float4(v0 - l0, v1 - l0, v2 - l1, v3 - l1);
    } else if (j < n) {
        float dv = g_dinv[j];
        float2 a = g_a2[j];
        float v0 = fmaf(dv, a.x, bb0);
        float v1 = fmaf(dv, a.y, bb1);
        float m = fmaxf(v0, v1);
        float lse = m + __logf(__expf(v0 - m) + __expf(v1 - m));
        out[2 * j + 0] = v0 - lse;
        out[2 * j + 1] = v1 - lse;
    }
}

// Launch helper: programmatic dependent launch (overlap with predecessor tail)
template <typename K, typename... Args>
static void launch_pdl(K kernel, int grid, int block, Args... args) {
    cudaLaunchConfig_t cfg = {};
    cfg.gridDim = dim3(grid, 1, 1);
    cfg.blockDim = dim3(block, 1, 1);
    cfg.dynamicSmemBytes = 0;
    cfg.stream = 0;
    cudaLaunchAttribute attr[1];
    attr[0].id = cudaLaunchAttributeProgrammaticStreamSerialization;
    attr[0].val.programmaticStreamSerializationAllowed = 1;
    cfg.attrs = attr;
    cfg.numAttrs = 1;
    cudaLaunchKernelEx(&cfg, kernel, args...);
}

extern "C" void kernel_launch(void* const* d_in, const int* in_sizes, int n_in,
                              void* d_out, int out_size) {
    const float* x  = (const float*)d_in[0];
    const int*   ei = (const int*)d_in[1];
    const float* W1 = (const float*)d_in[2];
    const float* b1 = (const float*)d_in[3];
    const float* W2 = (const float*)d_in[4];
    const float* b2 = (const float*)d_in[5];
    float* out = (float*)d_out;

    int n  = in_sizes[0];          // N nodes (x is [N,1])
    int ne = in_sizes[1] / 2;      // edge_index is [2, E]
    const int* src = ei;
    const int* dst = ei + ne;

    const int TN = 256;            // node kernels
    const int TE = 128;            // edge kernels (shallower per-CTA L1tex queues)
    int gridN4  = ((n + 3) / 4 + TN - 1) / TN;
    int gridN2t = ((n + 1) / 2 + TN - 1) / TN;
    int gridE4  = ((ne + 3) / 4 + TE - 1) / TE;

    k_count<<<gridE4, TE>>>(dst, ne);
    launch_pdl(k_prep,     gridN4,  TN, x, n);
    launch_pdl(k_scatter1, gridE4,  TE, src, dst, ne);
    launch_pdl(k_node,     gridN2t, TN, W1, b1, W2, n);
    launch_pdl(k_scatter2, gridE4,  TE, src, dst, ne);
    launch_pdl(k_final,    gridN2t, TN, b2, out, n);
}

// round 12
// speedup vs baseline: 1.0019x; 1.0019x over previous
#include <cuda_runtime.h>
#include <math.h>

#define NN 500000
#define NE 8000000

// Scratch (device globals — zero-initialized at load; g_deg is re-zeroed by
// k_prep after each use, so every kernel_launch call sees deg==0 on entry).
__device__ float g_deg[NN];
__device__ float g_dinv[NN];
__device__ float g_p[NN];            // x*dinv
__device__ float g_a1[NN];           // layer-1 accumulator, seeded with p (self-loop)
__device__ float2 g_q[NN];           // z*dinv per node (2 floats)
__device__ float2 g_a2[NN];          // layer-2 accumulator, seeded with q (self-loop)

// ---------------- count in-degree over dst (4 edges/thread) ----------------
__global__ void __launch_bounds__(256) k_count(const int* __restrict__ dst, int ne) {
    int i = blockIdx.x * blockDim.x + threadIdx.x;
    int e = i * 4;
    if (e + 4 <= ne) {
        int4 d = *reinterpret_cast<const int4*>(dst + e);
        atomicAdd(&g_deg[d.x], 1.0f);
        atomicAdd(&g_deg[d.y], 1.0f);
        atomicAdd(&g_deg[d.z], 1.0f);
        atomicAdd(&g_deg[d.w], 1.0f);
    } else {
        for (; e < ne; e++) atomicAdd(&g_deg[dst[e]], 1.0f);
    }
}

// -- dinv = rsqrt(deg+1); p = x*dinv; a1 = p (self-loop); deg re-zeroed; 4/thread --
__global__ void __launch_bounds__(256) k_prep(const float* __restrict__ x, int n) {
    int i = blockIdx.x * blockDim.x + threadIdx.x;
    int j = i * 4;
    if (j + 4 <= n) {
        // independent: input x (not written by k_count)
        float4 xv = *reinterpret_cast<const float4*>(x + j);
        cudaGridDependencySynchronize();   // wait for k_count's deg writes
        float4 dg = *reinterpret_cast<const float4*>(g_deg + j);
        float4 dv;
        dv.x = rsqrtf(dg.x + 1.0f);
        dv.y = rsqrtf(dg.y + 1.0f);
        dv.z = rsqrtf(dg.z + 1.0f);
        dv.w = rsqrtf(dg.w + 1.0f);
        *reinterpret_cast<float4*>(g_dinv + j) = dv;
        float4 pv = make_float4(xv.x * dv.x, xv.y * dv.y, xv.z * dv.z, xv.w * dv.w);
        *reinterpret_cast<float4*>(g_p + j) = pv;
        *reinterpret_cast<float4*>(g_a1 + j) = pv;   // self-loop contribution
        *reinterpret_cast<float4*>(g_deg + j) = make_float4(0.f, 0.f, 0.f, 0.f);
    } else if (j < n) {
        cudaGridDependencySynchronize();
        for (; j < n; j++) {
            float dv = rsqrtf(g_deg[j] + 1.0f);
            g_dinv[j] = dv;
            float pv = x[j] * dv;
            g_p[j] = pv;
            g_a1[j] = pv;
            g_deg[j] = 0.0f;
        }
    } else {
        cudaGridDependencySynchronize();
    }
}

// ---------------- layer-1 scalar scatter: a1[dst] += p[src] (4 edges/thread) --
__global__ void __launch_bounds__(256) k_scatter1(const int* __restrict__ src,
                                                  const int* __restrict__ dst, int ne) {
    int i = blockIdx.x * blockDim.x + threadIdx.x;
    int e = i * 4;
    if (e + 4 <= ne) {
        // independent: edge indices (input buffer, untouched by k_prep)
        int4 s = *reinterpret_cast<const int4*>(src + e);
        int4 d = *reinterpret_cast<const int4*>(dst + e);
        cudaGridDependencySynchronize();   // wait for k_prep's p/a1 writes
        float p0 = __ldcg(&g_p[s.x]);
        float p1 = __ldcg(&g_p[s.y]);
        float p2 = __ldcg(&g_p[s.z]);
        float p3 = __ldcg(&g_p[s.w]);
        atomicAdd(&g_a1[d.x], p0);
        atomicAdd(&g_a1[d.y], p1);
        atomicAdd(&g_a1[d.z], p2);
        atomicAdd(&g_a1[d.w], p3);
    } else {
        cudaGridDependencySynchronize();
        for (; e < ne; e++) atomicAdd(&g_a1[dst[e]], __ldcg(&g_p[src[e]]));
    }
}

// ---- per-node MLP (2 nodes/thread): q = dinv*(relu(dinv*a1*W1+b1)@W2); a2 = q ----
__global__ void __launch_bounds__(256) k_node(const float* __restrict__ W1,
                                              const float* __restrict__ b1,
                                              const float* __restrict__ W2, int n) {
    __shared__ float sW1[16], sb1[16], sW2[32];
    int t = threadIdx.x;
    if (t < 16) { sW1[t] = W1[t]; sb1[t] = b1[t]; }
    if (t < 32) { sW2[t] = W2[t]; }
    __syncthreads();
    cudaGridDependencySynchronize();       // wait for k_scatter1's a1 REDs
    int i = blockIdx.x * blockDim.x + t;
    int j = i * 2;
    if (j + 2 <= n) {
        float2 dv = *reinterpret_cast<const float2*>(g_dinv + j);
        float2 a1 = *reinterpret_cast<const float2*>(g_a1 + j);
        float s1a = dv.x * a1.x;
        float s1b = dv.y * a1.y;
        float z0a = 0.0f, z1a = 0.0f, z0b = 0.0f, z1b = 0.0f;
        #pragma unroll
        for (int k = 0; k < 16; k++) {
            float w1 = sW1[k], bb = sb1[k];
            float w20 = sW2[2 * k + 0], w21 = sW2[2 * k + 1];
            float ha = fmaxf(fmaf(s1a, w1, bb), 0.0f);
            float hb = fmaxf(fmaf(s1b, w1, bb), 0.0f);
            z0a = fmaf(ha, w20, z0a);
            z1a = fmaf(ha, w21, z1a);
            z0b = fmaf(hb, w20, z0b);
            z1b = fmaf(hb, w21, z1b);
        }
        float4 qq = make_float4(z0a * dv.x, z1a * dv.x, z0b * dv.y, z1b * dv.y);
        *reinterpret_cast<float4*>(reinterpret_cast<float*>(g_q) + 2 * j) = qq;
        *reinterpret_cast<float4*>(reinterpret_cast<float*>(g_a2) + 2 * j) = qq; // self-loop
    } else if (j < n) {
        float dv = g_dinv[j];
        float s1 = dv * g_a1[j];
        float z0 = 0.0f, z1 = 0.0f;
        #pragma unroll
        for (int k = 0; k < 16; k++) {
            float h = fmaxf(fmaf(s1, sW1[k], sb1[k]), 0.0f);
            z0 = fmaf(h, sW2[2 * k + 0], z0);
            z1 = fmaf(h, sW2[2 * k + 1], z1);
        }
        float2 qq = make_float2(z0 * dv, z1 * dv);
        g_q[j] = qq;
        g_a2[j] = qq;
    }
}

// ---------------- layer-2 vector scatter: a2[dst] += q[src] (float2 RED) ----
__global__ void __launch_bounds__(256) k_scatter2(const int* __restrict__ src,
                                                  const int* __restrict__ dst, int ne) {
    int i = blockIdx.x * blockDim.x + threadIdx.x;
    int e = i * 4;
    if (e + 4 <= ne) {
        int4 s = *reinterpret_cast<const int4*>(src + e);
        int4 d = *reinterpret_cast<const int4*>(dst + e);
        cudaGridDependencySynchronize();   // wait for k_node's q/a2 writes
        float2 q0 = __ldcg(&g_q[s.x]);
        float2 q1 = __ldcg(&g_q[s.y]);
        float2 q2 = __ldcg(&g_q[s.z]);
        float2 q3 = __ldcg(&g_q[s.w]);
        atomicAdd(&g_a2[d.x], q0);
        atomicAdd(&g_a2[d.y], q1);
        atomicAdd(&g_a2[d.z], q2);
        atomicAdd(&g_a2[d.w], q3);
    } else {
        cudaGridDependencySynchronize();
        for (; e < ne; e++) {
            atomicAdd(&g_a2[dst[e]], __ldcg(&g_q[src[e]]));
        }
    }
}

// ---------- finalize: out = log_softmax(dinv*a2 + b2), 2 nodes/thread ----------
__global__ void __launch_bounds__(256) k_final(const float* __restrict__ b2,
                                               float* __restrict__ out, int n) {
    int i = blockIdx.x * blockDim.x + threadIdx.x;
    int j = i * 2;
    float bb0 = __ldg(&b2[0]), bb1 = __ldg(&b2[1]);
    cudaGridDependencySynchronize();       // wait for k_scatter2's a2 REDs
    if (j + 2 <= n) {
        float2 dv2 = *reinterpret_cast<const float2*>(g_dinv + j);
        float4 a = *reinterpret_cast<const float4*>(reinterpret_cast<const float*>(g_a2) + 2 * j);
        float v0 = fmaf(dv2.x, a.x, bb0);
        float v1 = fmaf(dv2.x, a.y, bb1);
        float m0 = fmaxf(v0, v1);
        float l0 = m0 + __logf(__expf(v0 - m0) + __expf(v1 - m0));
        float v2 = fmaf(dv2.y, a.z, bb0);
        float v3 = fmaf(dv2.y, a.w, bb1);
        float m1 = fmaxf(v2, v3);
        float l1 = m1 + __logf(__expf(v2 - m1) + __expf(v3 - m1));
        *reinterpret_cast<float4*>(out + 2 * j) =
            make_float4(v0 - l0, v1 - l0, v2 - l1, v3 - l1);
    } else if (j < n) {
        float dv = g_dinv[j];
        float2 a = g_a2[j];
        float v0 = fmaf(dv, a.x, bb0);
        float v1 = fmaf(dv, a.y, bb1);
        float m = fmaxf(v0, v1);
        float lse = m + __logf(__expf(v0 - m) + __expf(v1 - m));
        out[2 * j + 0] = v0 - lse;
        out[2 * j + 1] = v1 - lse;
    }
}

// Launch helper: programmatic dependent launch (overlap with predecessor tail)
template <typename K, typename... Args>
static void launch_pdl(K kernel, int grid, int block, Args... args) {
    cudaLaunchConfig_t cfg = {};
    cfg.gridDim = dim3(grid, 1, 1);
    cfg.blockDim = dim3(block, 1, 1);
    cfg.dynamicSmemBytes = 0;
    cfg.stream = 0;
    cudaLaunchAttribute attr[1];
    attr[0].id = cudaLaunchAttributeProgrammaticStreamSerialization;
    attr[0].val.programmaticStreamSerializationAllowed = 1;
    cfg.attrs = attr;
    cfg.numAttrs = 1;
    cudaLaunchKernelEx(&cfg, kernel, args...);
}

extern "C" void kernel_launch(void* const* d_in, const int* in_sizes, int n_in,
                              void* d_out, int out_size) {
    const float* x  = (const float*)d_in[0];
    const int*   ei = (const int*)d_in[1];
    const float* W1 = (const float*)d_in[2];
    const float* b1 = (const float*)d_in[3];
    const float* W2 = (const float*)d_in[4];
    const float* b2 = (const float*)d_in[5];
    float* out = (float*)d_out;

    int n  = in_sizes[0];          // N nodes (x is [N,1])
    int ne = in_sizes[1] / 2;      // edge_index is [2, E]
    const int* src = ei;
    const int* dst = ei + ne;

    const int T = 256;
    int gridN4  = ((n + 3) / 4 + T - 1) / T;
    int gridN2t = ((n + 1) / 2 + T - 1) / T;
    int gridE4  = ((ne + 3) / 4 + T - 1) / T;

    k_count<<<gridE4, T>>>(dst, ne);
    launch_pdl(k_prep,     gridN4,  T, x, n);
    launch_pdl(k_scatter1, gridE4,  T, src, dst, ne);
    launch_pdl(k_node,     gridN2t, T, W1, b1, W2, n);
    launch_pdl(k_scatter2, gridE4,  T, src, dst, ne);
    launch_pdl(k_final,    gridN2t, T, b2, out, n);
}

// round 13
// speedup vs baseline: 1.0039x; 1.0019x over previous
#include <cuda_runtime.h>
#include <math.h>

#define NN 500000
#define NE 8000000

// Scratch (device globals — zero-initialized at load; g_deg is re-zeroed by
// k_prep after each use, so every kernel_launch call sees deg==0 on entry).
__device__ float g_deg[NN];
__device__ float g_dinv[NN];
__device__ float g_p[NN];            // x*dinv
__device__ float g_a1[NN];           // layer-1 accumulator, seeded with p (self-loop)
__device__ float2 g_q[NN];           // z*dinv per node (2 floats)
__device__ float2 g_a2[NN];          // layer-2 accumulator, seeded with q (self-loop)

// ---------------- count in-degree over dst (4 edges/thread) ----------------
__global__ void __launch_bounds__(256) k_count(const int* __restrict__ dst, int ne) {
    int i = blockIdx.x * blockDim.x + threadIdx.x;
    int e = i * 4;
    if (e + 4 <= ne) {
        int4 d = *reinterpret_cast<const int4*>(dst + e);
        atomicAdd(&g_deg[d.x], 1.0f);
        atomicAdd(&g_deg[d.y], 1.0f);
        atomicAdd(&g_deg[d.z], 1.0f);
        atomicAdd(&g_deg[d.w], 1.0f);
    } else {
        for (; e < ne; e++) atomicAdd(&g_deg[dst[e]], 1.0f);
    }
}

// -- dinv = rsqrt(deg+1); p = x*dinv; a1 = p (self-loop); deg re-zeroed; 4/thread --
__global__ void __launch_bounds__(256) k_prep(const float* __restrict__ x, int n) {
    int i = blockIdx.x * blockDim.x + threadIdx.x;
    int j = i * 4;
    if (j + 4 <= n) {
        // independent: input x (not written by k_count)
        float4 xv = *reinterpret_cast<const float4*>(x + j);
        cudaGridDependencySynchronize();   // wait for k_count's deg writes
        float4 dg = *reinterpret_cast<const float4*>(g_deg + j);
        float4 dv;
        dv.x = rsqrtf(dg.x + 1.0f);
        dv.y = rsqrtf(dg.y + 1.0f);
        dv.z = rsqrtf(dg.z + 1.0f);
        dv.w = rsqrtf(dg.w + 1.0f);
        *reinterpret_cast<float4*>(g_dinv + j) = dv;
        float4 pv = make_float4(xv.x * dv.x, xv.y * dv.y, xv.z * dv.z, xv.w * dv.w);
        *reinterpret_cast<float4*>(g_p + j) = pv;
        *reinterpret_cast<float4*>(g_a1 + j) = pv;   // self-loop contribution
        *reinterpret_cast<float4*>(g_deg + j) = make_float4(0.f, 0.f, 0.f, 0.f);
    } else if (j < n) {
        cudaGridDependencySynchronize();
        for (; j < n; j++) {
            float dv = rsqrtf(g_deg[j] + 1.0f);
            g_dinv[j] = dv;
            float pv = x[j] * dv;
            g_p[j] = pv;
            g_a1[j] = pv;
            g_deg[j] = 0.0f;
        }
    } else {
        cudaGridDependencySynchronize();
    }
}

// ---------------- layer-1 scalar scatter: a1[dst] += p[src] (4 edges/thread) --
__global__ void __launch_bounds__(256) k_scatter1(const int* __restrict__ src,
                                                  const int* __restrict__ dst, int ne) {
    int i = blockIdx.x * blockDim.x + threadIdx.x;
    int e = i * 4;
    if (e + 4 <= ne) {
        // independent: edge indices (input buffer, untouched by k_prep)
        int4 s = *reinterpret_cast<const int4*>(src + e);
        int4 d = *reinterpret_cast<const int4*>(dst + e);
        cudaGridDependencySynchronize();   // wait for k_prep's p/a1 writes
        float p0 = __ldcg(&g_p[s.x]);
        float p1 = __ldcg(&g_p[s.y]);
        float p2 = __ldcg(&g_p[s.z]);
        float p3 = __ldcg(&g_p[s.w]);
        atomicAdd(&g_a1[d.x], p0);
        atomicAdd(&g_a1[d.y], p1);
        atomicAdd(&g_a1[d.z], p2);
        atomicAdd(&g_a1[d.w], p3);
    } else {
        cudaGridDependencySynchronize();
        for (; e < ne; e++) atomicAdd(&g_a1[dst[e]], __ldcg(&g_p[src[e]]));
    }
}

// ---- per-node MLP (2 nodes/thread): q = dinv*(relu(dinv*a1*W1+b1)@W2); a2 = q ----
// dinv was written by k_prep (grand-predecessor, complete before scatter1 finished)
// so it is safe to prefetch before the grid-dependency sync.
__global__ void __launch_bounds__(256) k_node(const float* __restrict__ W1,
                                              const float* __restrict__ b1,
                                              const float* __restrict__ W2, int n) {
    __shared__ float sW1[16], sb1[16], sW2[32];
    int t = threadIdx.x;
    if (t < 16) { sW1[t] = W1[t]; sb1[t] = b1[t]; }
    if (t < 32) { sW2[t] = W2[t]; }
    __syncthreads();
    int i = blockIdx.x * blockDim.x + t;
    int j = i * 2;
    if (j + 2 <= n) {
        float2 dv = *reinterpret_cast<const float2*>(g_dinv + j);  // prefetch (safe: k_prep done)
        cudaGridDependencySynchronize();       // wait for k_scatter1's a1 REDs
        float2 a1 = *reinterpret_cast<const float2*>(g_a1 + j);
        float s1a = dv.x * a1.x;
        float s1b = dv.y * a1.y;
        float z0a = 0.0f, z1a = 0.0f, z0b = 0.0f, z1b = 0.0f;
        #pragma unroll
        for (int k = 0; k < 16; k++) {
            float w1 = sW1[k], bb = sb1[k];
            float w20 = sW2[2 * k + 0], w21 = sW2[2 * k + 1];
            float ha = fmaxf(fmaf(s1a, w1, bb), 0.0f);
            float hb = fmaxf(fmaf(s1b, w1, bb), 0.0f);
            z0a = fmaf(ha, w20, z0a);
            z1a = fmaf(ha, w21, z1a);
            z0b = fmaf(hb, w20, z0b);
            z1b = fmaf(hb, w21, z1b);
        }
        float4 qq = make_float4(z0a * dv.x, z1a * dv.x, z0b * dv.y, z1b * dv.y);
        *reinterpret_cast<float4*>(reinterpret_cast<float*>(g_q) + 2 * j) = qq;
        *reinterpret_cast<float4*>(reinterpret_cast<float*>(g_a2) + 2 * j) = qq; // self-loop
    } else if (j < n) {
        cudaGridDependencySynchronize();
        float dv = g_dinv[j];
        float s1 = dv * g_a1[j];
        float z0 = 0.0f, z1 = 0.0f;
        #pragma unroll
        for (int k = 0; k < 16; k++) {
            float h = fmaxf(fmaf(s1, sW1[k], sb1[k]), 0.0f);
            z0 = fmaf(h, sW2[2 * k + 0], z0);
            z1 = fmaf(h, sW2[2 * k + 1], z1);
        }
        float2 qq = make_float2(z0 * dv, z1 * dv);
        g_q[j] = qq;
        g_a2[j] = qq;
    } else {
        cudaGridDependencySynchronize();
    }
}

// ---------------- layer-2 vector scatter: a2[dst] += q[src] (float2 RED) ----
__global__ void __launch_bounds__(256) k_scatter2(const int* __restrict__ src,
                                                  const int* __restrict__ dst, int ne) {
    int i = blockIdx.x * blockDim.x + threadIdx.x;
    int e = i * 4;
    if (e + 4 <= ne) {
        int4 s = *reinterpret_cast<const int4*>(src + e);
        int4 d = *reinterpret_cast<const int4*>(dst + e);
        cudaGridDependencySynchronize();   // wait for k_node's q/a2 writes
        float2 q0 = __ldcg(&g_q[s.x]);
        float2 q1 = __ldcg(&g_q[s.y]);
        float2 q2 = __ldcg(&g_q[s.z]);
        float2 q3 = __ldcg(&g_q[s.w]);
        atomicAdd(&g_a2[d.x], q0);
        atomicAdd(&g_a2[d.y], q1);
        atomicAdd(&g_a2[d.z], q2);
        atomicAdd(&g_a2[d.w], q3);
    } else {
        cudaGridDependencySynchronize();
        for (; e < ne; e++) {
            atomicAdd(&g_a2[dst[e]], __ldcg(&g_q[src[e]]));
        }
    }
}

// ---------- finalize: out = log_softmax(dinv*a2 + b2), 2 nodes/thread ----------
__global__ void __launch_bounds__(256) k_final(const float* __restrict__ b2,
                                               float* __restrict__ out, int n) {
    int i = blockIdx.x * blockDim.x + threadIdx.x;
    int j = i * 2;
    float bb0 = __ldg(&b2[0]), bb1 = __ldg(&b2[1]);
    if (j + 2 <= n) {
        float2 dv2 = *reinterpret_cast<const float2*>(g_dinv + j);  // prefetch (safe: k_prep done)
        cudaGridDependencySynchronize();       // wait for k_scatter2's a2 REDs
        float4 a = *reinterpret_cast<const float4*>(reinterpret_cast<const float*>(g_a2) + 2 * j);
        float v0 = fmaf(dv2.x, a.x, bb0);
        float v1 = fmaf(dv2.x, a.y, bb1);
        float m0 = fmaxf(v0, v1);
        float l0 = m0 + __logf(__expf(v0 - m0) + __expf(v1 - m0));
        float v2 = fmaf(dv2.y, a.z, bb0);
        float v3 = fmaf(dv2.y, a.w, bb1);
        float m1 = fmaxf(v2, v3);
        float l1 = m1 + __logf(__expf(v2 - m1) + __expf(v3 - m1));
        *reinterpret_cast<float4*>(out + 2 * j) =
            make_float4(v0 - l0, v1 - l0, v2 - l1, v3 - l1);
    } else if (j < n) {
        cudaGridDependencySynchronize();
        float dv = g_dinv[j];
        float2 a = g_a2[j];
        float v0 = fmaf(dv, a.x, bb0);
        float v1 = fmaf(dv, a.y, bb1);
        float m = fmaxf(v0, v1);
        float lse = m + __logf(__expf(v0 - m) + __expf(v1 - m));
        out[2 * j + 0] = v0 - lse;
        out[2 * j + 1] = v1 - lse;
    } else {
        cudaGridDependencySynchronize();
    }
}

// Launch helper: programmatic dependent launch (overlap with predecessor tail)
template <typename K, typename... Args>
static void launch_pdl(K kernel, int grid, int block, Args... args) {
    cudaLaunchConfig_t cfg = {};
    cfg.gridDim = dim3(grid, 1, 1);
    cfg.blockDim = dim3(block, 1, 1);
    cfg.dynamicSmemBytes = 0;
    cfg.stream = 0;
    cudaLaunchAttribute attr[1];
    attr[0].id = cudaLaunchAttributeProgrammaticStreamSerialization;
    attr[0].val.programmaticStreamSerializationAllowed = 1;
    cfg.attrs = attr;
    cfg.numAttrs = 1;
    cudaLaunchKernelEx(&cfg, kernel, args...);
}

extern "C" void kernel_launch(void* const* d_in, const int* in_sizes, int n_in,
                              void* d_out, int out_size) {
    const float* x  = (const float*)d_in[0];
    const int*   ei = (const int*)d_in[1];
    const float* W1 = (const float*)d_in[2];
    const float* b1 = (const float*)d_in[3];
    const float* W2 = (const float*)d_in[4];
    const float* b2 = (const float*)d_in[5];
    float* out = (float*)d_out;

    int n  = in_sizes[0];          // N nodes (x is [N,1])
    int ne = in_sizes[1] / 2;      // edge_index is [2, E]
    const int* src = ei;
    const int* dst = ei + ne;

    const int T = 256;
    int gridN4  = ((n + 3) / 4 + T - 1) / T;
    int gridN2t = ((n + 1) / 2 + T - 1) / T;
    int gridE4  = ((ne + 3) / 4 + T - 1) / T;

    k_count<<<gridE4, T>>>(dst, ne);
    launch_pdl(k_prep,     gridN4,  T, x, n);
    launch_pdl(k_scatter1, gridE4,  T, src, dst, ne);
    launch_pdl(k_node,     gridN2t, T, W1, b1, W2, n);
    launch_pdl(k_scatter2, gridE4,  T, src, dst, ne);
    launch_pdl(k_final,    gridN2t, T, b2, out, n);
}

// round 14
// speedup vs baseline: 1.0124x; 1.0086x over previous
#include <cuda_runtime.h>
#include <math.h>

#define NN 500000
#define NE 8000000

// Scratch (device globals — zero-initialized at load; g_deg is re-zeroed by
// k_prep after each use, so every kernel_launch call sees deg==0 on entry).
__device__ float g_deg[NN];
__device__ float g_dinv[NN];
__device__ float g_p[NN];            // x*dinv
__device__ float g_a1[NN];           // layer-1 accumulator, seeded with p (self-loop)
__device__ float2 g_q[NN];           // z*dinv per node (2 floats)
__device__ float2 g_a2[NN];          // layer-2 accumulator, seeded with q (self-loop)

// ---------------- count in-degree over dst (4 edges/thread) ----------------
__global__ void __launch_bounds__(256) k_count(const int* __restrict__ dst, int ne) {
    int i = blockIdx.x * blockDim.x + threadIdx.x;
    int e = i * 4;
    if (e + 4 <= ne) {
        int4 d = __ldcs(reinterpret_cast<const int4*>(dst + e));  // streaming, no reuse
        atomicAdd(&g_deg[d.x], 1.0f);
        atomicAdd(&g_deg[d.y], 1.0f);
        atomicAdd(&g_deg[d.z], 1.0f);
        atomicAdd(&g_deg[d.w], 1.0f);
    } else {
        for (; e < ne; e++) atomicAdd(&g_deg[dst[e]], 1.0f);
    }
}

// -- dinv = rsqrt(deg+1); p = x*dinv; a1 = p (self-loop); deg re-zeroed; 4/thread --
__global__ void __launch_bounds__(256) k_prep(const float* __restrict__ x, int n) {
    int i = blockIdx.x * blockDim.x + threadIdx.x;
    int j = i * 4;
    if (j + 4 <= n) {
        // independent: input x (not written by k_count)
        float4 xv = __ldcs(reinterpret_cast<const float4*>(x + j));
        cudaGridDependencySynchronize();   // wait for k_count's deg writes
        float4 dg = *reinterpret_cast<const float4*>(g_deg + j);
        float4 dv;
        dv.x = rsqrtf(dg.x + 1.0f);
        dv.y = rsqrtf(dg.y + 1.0f);
        dv.z = rsqrtf(dg.z + 1.0f);
        dv.w = rsqrtf(dg.w + 1.0f);
        *reinterpret_cast<float4*>(g_dinv + j) = dv;
        float4 pv = make_float4(xv.x * dv.x, xv.y * dv.y, xv.z * dv.z, xv.w * dv.w);
        *reinterpret_cast<float4*>(g_p + j) = pv;
        *reinterpret_cast<float4*>(g_a1 + j) = pv;   // self-loop contribution
        *reinterpret_cast<float4*>(g_deg + j) = make_float4(0.f, 0.f, 0.f, 0.f);
    } else if (j < n) {
        cudaGridDependencySynchronize();
        for (; j < n; j++) {
            float dv = rsqrtf(g_deg[j] + 1.0f);
            g_dinv[j] = dv;
            float pv = x[j] * dv;
            g_p[j] = pv;
            g_a1[j] = pv;
            g_deg[j] = 0.0f;
        }
    } else {
        cudaGridDependencySynchronize();
    }
}

// ---------------- layer-1 scalar scatter: a1[dst] += p[src] (4 edges/thread) --
__global__ void __launch_bounds__(256) k_scatter1(const int* __restrict__ src,
                                                  const int* __restrict__ dst, int ne) {
    int i = blockIdx.x * blockDim.x + threadIdx.x;
    int e = i * 4;
    if (e + 4 <= ne) {
        // independent: edge indices (input buffer, untouched by k_prep)
        int4 s = __ldcs(reinterpret_cast<const int4*>(src + e));
        int4 d = __ldcs(reinterpret_cast<const int4*>(dst + e));
        cudaGridDependencySynchronize();   // wait for k_prep's p/a1 writes
        float p0 = __ldcg(&g_p[s.x]);
        float p1 = __ldcg(&g_p[s.y]);
        float p2 = __ldcg(&g_p[s.z]);
        float p3 = __ldcg(&g_p[s.w]);
        atomicAdd(&g_a1[d.x], p0);
        atomicAdd(&g_a1[d.y], p1);
        atomicAdd(&g_a1[d.z], p2);
        atomicAdd(&g_a1[d.w], p3);
    } else {
        cudaGridDependencySynchronize();
        for (; e < ne; e++) atomicAdd(&g_a1[dst[e]], __ldcg(&g_p[src[e]]));
    }
}

// ---- per-node MLP (2 nodes/thread): q = dinv*(relu(dinv*a1*W1+b1)@W2); a2 = q ----
// dinv was written by k_prep (grand-predecessor, complete before scatter1 finished)
// so it is safe to prefetch before the grid-dependency sync.
__global__ void __launch_bounds__(256) k_node(const float* __restrict__ W1,
                                              const float* __restrict__ b1,
                                              const float* __restrict__ W2, int n) {
    __shared__ float sW1[16], sb1[16], sW2[32];
    int t = threadIdx.x;
    if (t < 16) { sW1[t] = W1[t]; sb1[t] = b1[t]; }
    if (t < 32) { sW2[t] = W2[t]; }
    __syncthreads();
    int i = blockIdx.x * blockDim.x + t;
    int j = i * 2;
    if (j + 2 <= n) {
        float2 dv = *reinterpret_cast<const float2*>(g_dinv + j);  // prefetch (safe: k_prep done)
        cudaGridDependencySynchronize();       // wait for k_scatter1's a1 REDs
        float2 a1 = *reinterpret_cast<const float2*>(g_a1 + j);
        float s1a = dv.x * a1.x;
        float s1b = dv.y * a1.y;
        float z0a = 0.0f, z1a = 0.0f, z0b = 0.0f, z1b = 0.0f;
        #pragma unroll
        for (int k = 0; k < 16; k++) {
            float w1 = sW1[k], bb = sb1[k];
            float w20 = sW2[2 * k + 0], w21 = sW2[2 * k + 1];
            float ha = fmaxf(fmaf(s1a, w1, bb), 0.0f);
            float hb = fmaxf(fmaf(s1b, w1, bb), 0.0f);
            z0a = fmaf(ha, w20, z0a);
            z1a = fmaf(ha, w21, z1a);
            z0b = fmaf(hb, w20, z0b);
            z1b = fmaf(hb, w21, z1b);
        }
        float4 qq = make_float4(z0a * dv.x, z1a * dv.x, z0b * dv.y, z1b * dv.y);
        *reinterpret_cast<float4*>(reinterpret_cast<float*>(g_q) + 2 * j) = qq;
        *reinterpret_cast<float4*>(reinterpret_cast<float*>(g_a2) + 2 * j) = qq; // self-loop
    } else if (j < n) {
        cudaGridDependencySynchronize();
        float dv = g_dinv[j];
        float s1 = dv * g_a1[j];
        float z0 = 0.0f, z1 = 0.0f;
        #pragma unroll
        for (int k = 0; k < 16; k++) {
            float h = fmaxf(fmaf(s1, sW1[k], sb1[k]), 0.0f);
            z0 = fmaf(h, sW2[2 * k + 0], z0);
            z1 = fmaf(h, sW2[2 * k + 1], z1);
        }
        float2 qq = make_float2(z0 * dv, z1 * dv);
        g_q[j] = qq;
        g_a2[j] = qq;
    } else {
        cudaGridDependencySynchronize();
    }
}

// ---------------- layer-2 vector scatter: a2[dst] += q[src] (float2 RED) ----
__global__ void __launch_bounds__(256) k_scatter2(const int* __restrict__ src,
                                                  const int* __restrict__ dst, int ne) {
    int i = blockIdx.x * blockDim.x + threadIdx.x;
    int e = i * 4;
    if (e + 4 <= ne) {
        int4 s = __ldcs(reinterpret_cast<const int4*>(src + e));
        int4 d = __ldcs(reinterpret_cast<const int4*>(dst + e));
        cudaGridDependencySynchronize();   // wait for k_node's q/a2 writes
        float2 q0 = __ldcg(&g_q[s.x]);
        float2 q1 = __ldcg(&g_q[s.y]);
        float2 q2 = __ldcg(&g_q[s.z]);
        float2 q3 = __ldcg(&g_q[s.w]);
        atomicAdd(&g_a2[d.x], q0);
        atomicAdd(&g_a2[d.y], q1);
        atomicAdd(&g_a2[d.z], q2);
        atomicAdd(&g_a2[d.w], q3);
    } else {
        cudaGridDependencySynchronize();
        for (; e < ne; e++) {
            atomicAdd(&g_a2[dst[e]], __ldcg(&g_q[src[e]]));
        }
    }
}

// ---------- finalize: out = log_softmax(dinv*a2 + b2), 2 nodes/thread ----------
__global__ void __launch_bounds__(256) k_final(const float* __restrict__ b2,
                                               float* __restrict__ out, int n) {
    int i = blockIdx.x * blockDim.x + threadIdx.x;
    int j = i * 2;
    float bb0 = __ldg(&b2[0]), bb1 = __ldg(&b2[1]);
    if (j + 2 <= n) {
        float2 dv2 = *reinterpret_cast<const float2*>(g_dinv + j);  // prefetch (safe: k_prep done)
        cudaGridDependencySynchronize();       // wait for k_scatter2's a2 REDs
        float4 a = *reinterpret_cast<const float4*>(reinterpret_cast<const float*>(g_a2) + 2 * j);
        float v0 = fmaf(dv2.x, a.x, bb0);
        float v1 = fmaf(dv2.x, a.y, bb1);
        float m0 = fmaxf(v0, v1);
        float l0 = m0 + __logf(__expf(v0 - m0) + __expf(v1 - m0));
        float v2 = fmaf(dv2.y, a.z, bb0);
        float v3 = fmaf(dv2.y, a.w, bb1);
        float m1 = fmaxf(v2, v3);
        float l1 = m1 + __logf(__expf(v2 - m1) + __expf(v3 - m1));
        *reinterpret_cast<float4*>(out + 2 * j) =
            make_float4(v0 - l0, v1 - l0, v2 - l1, v3 - l1);
    } else if (j < n) {
        cudaGridDependencySynchronize();
        float dv = g_dinv[j];
        float2 a = g_a2[j];
        float v0 = fmaf(dv, a.x, bb0);
        float v1 = fmaf(dv, a.y, bb1);
        float m = fmaxf(v0, v1);
        float lse = m + __logf(__expf(v0 - m) + __expf(v1 - m));
        out[2 * j + 0] = v0 - lse;
        out[2 * j + 1] = v1 - lse;
    } else {
        cudaGridDependencySynchronize();
    }
}

// Launch helper: programmatic dependent launch (overlap with predecessor tail)
template <typename K, typename... Args>
static void launch_pdl(K kernel, int grid, int block, Args... args) {
    cudaLaunchConfig_t cfg = {};
    cfg.gridDim = dim3(grid, 1, 1);
    cfg.blockDim = dim3(block, 1, 1);
    cfg.dynamicSmemBytes = 0;
    cfg.stream = 0;
    cudaLaunchAttribute attr[1];
    attr[0].id = cudaLaunchAttributeProgrammaticStreamSerialization;
    attr[0].val.programmaticStreamSerializationAllowed = 1;
    cfg.attrs = attr;
    cfg.numAttrs = 1;
    cudaLaunchKernelEx(&cfg, kernel, args...);
}

extern "C" void kernel_launch(void* const* d_in, const int* in_sizes, int n_in,
                              void* d_out, int out_size) {
    const float* x  = (const float*)d_in[0];
    const int*   ei = (const int*)d_in[1];
    const float* W1 = (const float*)d_in[2];
    const float* b1 = (const float*)d_in[3];
    const float* W2 = (const float*)d_in[4];
    const float* b2 = (const float*)d_in[5];
    float* out = (float*)d_out;

    int n  = in_sizes[0];          // N nodes (x is [N,1])
    int ne = in_sizes[1] / 2;      // edge_index is [2, E]
    const int* src = ei;
    const int* dst = ei + ne;

    const int T = 256;
    int gridN4  = ((n + 3) / 4 + T - 1) / T;
    int gridN2t = ((n + 1) / 2 + T - 1) / T;
    int gridE4  = ((ne + 3) / 4 + T - 1) / T;

    k_count<<<gridE4, T>>>(dst, ne);
    launch_pdl(k_prep,     gridN4,  T, x, n);
    launch_pdl(k_scatter1, gridE4,  T, src, dst, ne);
    launch_pdl(k_node,     gridN2t, T, W1, b1, W2, n);
    launch_pdl(k_scatter2, gridE4,  T, src, dst, ne);
    launch_pdl(k_final,    gridN2t, T, b2, out, n);
}